// round 15
// baseline (speedup 1.0000x reference)
#include <cuda_runtime.h>
#include <cuda_fp16.h>
#include <math.h>
#include <stdint.h>

// ---------------- problem dims (fixed) ----------------
#define NB   2
#define LT   512
#define NI   2048
#define DM   512
#define NHD  4
#define HDD  128
#define FFD  2048
#define KVL  2560
#define E6   3072
#define MT   (NB*LT)
#define MI   (NB*NI)
#define MALL (MT+MI)
#define SCALE_C 0.08838834764831845f
#define LOG2E 1.44269504f
#define BIGR (1<<30)

// ---------------- scratch ----------------
__device__ __align__(256) float  d_e_img[NB*E6];
__device__ __align__(256) float  d_e_txt[NB*E6];
__device__ __align__(256) float  d_eff[NB];
__device__ __align__(256) float  d_mod[NB*NHD*NI];
__device__ __align__(256) __half d_nrm[MALL*DM];
__device__ __align__(256) __half d_Qc[NB*NHD*KVL*HDD];
__device__ __align__(256) __half d_Kc[NB*NHD*KVL*HDD];
__device__ __align__(256) __half d_VT[NB*NHD*HDD*KVL];
__device__ __align__(256) __half d_ap[MALL*DM];
__device__ __align__(256) __half d_h[MALL*FFD];
__device__ __align__(256) float  d_c[MALL*DM];
// half weights
__device__ __align__(256) __half d_wq_t[1536*DM];
__device__ __align__(256) __half d_wq_i[1536*DM];
__device__ __align__(256) __half d_wo_t[DM*DM];
__device__ __align__(256) __half d_wo_i[DM*DM];
__device__ __align__(256) __half d_w1_t[FFD*DM];
__device__ __align__(256) __half d_w1_i[FFD*DM];
__device__ __align__(256) __half d_w2_t[DM*FFD];
__device__ __align__(256) __half d_w2_i[DM*FFD];

// ---------------- helpers ----------------
__device__ __forceinline__ float warpSum(float v){
  #pragma unroll
  for (int o=16;o>0;o>>=1) v += __shfl_xor_sync(0xffffffffu, v, o);
  return v;
}
__device__ __forceinline__ uint32_t sptr(const void* p){
  uint32_t r;
  asm("{ .reg .u64 t; cvta.to.shared.u64 t, %1; cvt.u32.u64 %0, t; }" : "=r"(r) : "l"(p));
  return r;
}
__device__ __forceinline__ float geluf(float x){
  float t = tanhf(0.7978845608028654f*(x + 0.044715f*x*x*x));
  return 0.5f*x*(1.f+t);
}
#define HMMA(acc, a, b) \
  asm volatile( \
    "mma.sync.aligned.m16n8k16.row.col.f32.f16.f16.f32 " \
    "{%0,%1,%2,%3}, {%4,%5,%6,%7}, {%8,%9}, {%0,%1,%2,%3};" \
    : "+f"((acc)[0]), "+f"((acc)[1]), "+f"((acc)[2]), "+f"((acc)[3]) \
    : "r"((a)[0]), "r"((a)[1]), "r"((a)[2]), "r"((a)[3]), \
      "r"((b)[0]), "r"((b)[1]))
#define LDMX4(r0,r1,r2,r3, addr) \
  asm volatile("ldmatrix.sync.aligned.m8n8.x4.shared.b16 {%0,%1,%2,%3}, [%4];" \
    : "=r"(r0), "=r"(r1), "=r"(r2), "=r"(r3) : "r"(addr))
#define CPA16(dst, src) \
  asm volatile("cp.async.cg.shared.global [%0], [%1], 16;" :: "r"(dst), "l"(src))

// ================= fp16 mma.sync batched GEMM, K-chunk 64, fused epilogues =================
// MTS = warp m16-tiles (4 -> 128-row CTA tile, 2 -> 64-row). MINB = min CTAs/SM.
#define TSH 72
#define STAGE_B_H (128*TSH)

template<int MTS, int MINB>
__global__ __launch_bounds__(256, MINB) void tgemm(
    const __half* __restrict__ A, const __half* __restrict__ B1,
    const __half* __restrict__ B2, int msplit,
    void* __restrict__ C, int N, int K, int ldc,
    long long sA, long long sB,
    int rsplit, int zdiv, long long sCt, long long sCi, long long sCh, long long cbase,
    float alpha, const float* __restrict__ alphas, int adiv, int arsplit,
    int ep,
    const float* __restrict__ epRt, const float* __restrict__ epRi,
    const float* __restrict__ epEt, const float* __restrict__ epEi,
    const float* __restrict__ epBt, const float* __restrict__ epBi, int go,
    const float* __restrict__ ropep, const float* __restrict__ modp,
    __half* __restrict__ Qp, __half* __restrict__ Kp, __half* __restrict__ Vp)
{
  constexpr int CTAM = MTS*32;
  constexpr int STAGE_A_H = CTAM*TSH;
  extern __shared__ __half smh[];
  __half* As = smh;
  __half* Bs = smh + 2*STAGE_A_H;

  const int tid = threadIdx.x;
  const int z   = blockIdx.z;
  const long long bm = (long long)blockIdx.y * CTAM;
  const long long bn = (long long)blockIdx.x * 128;

  const __half* Ab = A + z*sA + bm*K;
  const __half* Bsel = (bm < msplit) ? B1 : B2;
  const __half* Bb = Bsel + z*sB + bn*K;

  float alp = ((int)bm < arsplit) ? alpha : alphas[z/adiv];
  long long zoff = ((int)bm < rsplit)
      ? (long long)(z/zdiv)*sCt + (long long)(z%zdiv)*sCh
      : cbase + (long long)(z/zdiv)*sCi + (long long)(z%zdiv)*sCh;

  const int lw  = tid & 31;
  const int w   = tid >> 5;
  const int wr  = (w >> 2) * (MTS*16);
  const int wc  = (w & 3) * 32;
  const int g   = lw >> 2;
  const int tg  = lw & 3;

  constexpr int ASH  = (MTS == 4) ? 1 : 2;
  constexpr int ANSEG = (MTS == 4) ? 4 : 2;
  const int a_lrow = tid >> ASH;
  const int a_lsel = (tid & ((1<<ASH)-1)) * (ANSEG*8);
  const int b_lrow = tid >> 1;
  const int b_lsel = (tid & 1) * 32;

  const int a_row = lw & 15;
  const int a_kh  = (lw >> 4) * 8;
  uint32_t aoff[MTS];
  #pragma unroll
  for (int mt = 0; mt < MTS; mt++)
    aoff[mt] = (uint32_t)(((wr + mt*16 + a_row)*TSH + a_kh) * 2);
  const int b_row = (lw & 7) + ((lw >> 4) & 1) * 8;
  const int b_kh  = ((lw >> 3) & 1) * 8;
  uint32_t boff[2];
  #pragma unroll
  for (int n2 = 0; n2 < 2; n2++)
    boff[n2] = (uint32_t)(((wc + n2*16 + b_row)*TSH + b_kh) * 2);

  const uint32_t Abase = sptr(As);
  const uint32_t Bbase = sptr(Bs);

  float acc[MTS][4][4];
  #pragma unroll
  for (int i=0;i<MTS;i++)
    #pragma unroll
    for (int j=0;j<4;j++)
      #pragma unroll
      for (int q=0;q<4;q++) acc[i][j][q] = 0.f;

  const int nch = K >> 6;

  auto load_chunk = [&](int c, int st){
    const __half* Ag = Ab + (long long)a_lrow*K + c*64 + a_lsel;
    uint32_t da = sptr(As + st*STAGE_A_H + a_lrow*TSH + a_lsel);
    #pragma unroll
    for (int j = 0; j < ANSEG; j++) CPA16(da + j*16, Ag + j*8);
    const __half* Bg = Bb + (long long)b_lrow*K + c*64 + b_lsel;
    uint32_t db = sptr(Bs + st*STAGE_B_H + b_lrow*TSH + b_lsel);
    #pragma unroll
    for (int j = 0; j < 4; j++) CPA16(db + j*16, Bg + j*8);
    asm volatile("cp.async.commit_group;");
  };

  load_chunk(0, 0);

  for (int i = 0; i < nch; i++){
    int st = i & 1;
    if (i + 1 < nch){
      load_chunk(i+1, st^1);
      asm volatile("cp.async.wait_group 1;" ::: "memory");
    } else {
      asm volatile("cp.async.wait_group 0;" ::: "memory");
    }
    __syncthreads();

    uint32_t sa = Abase + st*STAGE_A_H*2;
    uint32_t sb = Bbase + st*STAGE_B_H*2;

    #pragma unroll
    for (int ks = 0; ks < 4; ks++){
      uint32_t koff = ks*32;
      uint32_t af[MTS][4];
      #pragma unroll
      for (int mt = 0; mt < MTS; mt++)
        LDMX4(af[mt][0], af[mt][1], af[mt][2], af[mt][3], sa + aoff[mt] + koff);
      uint32_t bf[4][2];
      #pragma unroll
      for (int n2 = 0; n2 < 2; n2++)
        LDMX4(bf[n2*2][0], bf[n2*2][1], bf[n2*2+1][0], bf[n2*2+1][1], sb + boff[n2] + koff);
      #pragma unroll
      for (int mt = 0; mt < MTS; mt++)
        #pragma unroll
        for (int nt = 0; nt < 4; nt++)
          HMMA(acc[mt][nt], af[mt], bf[nt]);
    }
    __syncthreads();
  }

  // -------- epilogue --------
  if (ep == 1){
    __half* Cb = (__half*)C + zoff;
    #pragma unroll
    for (int mt = 0; mt < MTS; mt++){
      long long r0 = bm + wr + mt*16 + g;
      #pragma unroll
      for (int nt = 0; nt < 4; nt++){
        long long c0 = bn + wc + nt*8 + 2*tg;
        *(__half2*)(Cb + r0*ldc + c0)     = __floats2half2_rn(acc[mt][nt][0]*alp, acc[mt][nt][1]*alp);
        *(__half2*)(Cb + (r0+8)*ldc + c0) = __floats2half2_rn(acc[mt][nt][2]*alp, acc[mt][nt][3]*alp);
      }
    }
  } else if (ep == 0){
    float* Cb = (float*)C + zoff;
    #pragma unroll
    for (int mt = 0; mt < MTS; mt++){
      long long r0 = bm + wr + mt*16 + g;
      #pragma unroll
      for (int nt = 0; nt < 4; nt++){
        long long c0 = bn + wc + nt*8 + 2*tg;
        *(float2*)(Cb + r0*ldc + c0)     = make_float2(acc[mt][nt][0]*alp, acc[mt][nt][1]*alp);
        *(float2*)(Cb + (r0+8)*ldc + c0) = make_float2(acc[mt][nt][2]*alp, acc[mt][nt][3]*alp);
      }
    }
  } else if (ep == 2){
    float* Cb = (float*)C;
    #pragma unroll
    for (int mt = 0; mt < MTS; mt++){
      int r0 = (int)(bm + wr + mt*16 + g);
      #pragma unroll
      for (int half_ = 0; half_ < 2; half_++){
        int r = r0 + half_*8;
        int isT = (r < MT);
        int bb = isT ? (r/LT) : ((r-MT)/NI);
        const float* gate = (isT ? epEt : epEi) + bb*E6 + go;
        const float* R = isT ? (epRt + (long long)r*DM) : (epRi + (long long)(r-MT)*DM);
        #pragma unroll
        for (int nt = 0; nt < 4; nt++){
          int c0 = (int)(bn + wc + nt*8 + 2*tg);
          float a0 = acc[mt][nt][half_*2+0], a1 = acc[mt][nt][half_*2+1];
          float2 o = make_float2(R[c0] + gate[c0]*a0, R[c0+1] + gate[c0+1]*a1);
          *(float2*)(Cb + (long long)r*ldc + c0) = o;
        }
      }
    }
  } else if (ep == 3){
    __half* Cb = (__half*)C;
    #pragma unroll
    for (int mt = 0; mt < MTS; mt++){
      int r0 = (int)(bm + wr + mt*16 + g);
      #pragma unroll
      for (int half_ = 0; half_ < 2; half_++){
        int r = r0 + half_*8;
        const float* bias = (r < MT) ? epBt : epBi;
        #pragma unroll
        for (int nt = 0; nt < 4; nt++){
          int c0 = (int)(bn + wc + nt*8 + 2*tg);
          float a0 = geluf(acc[mt][nt][half_*2+0] + bias[c0]);
          float a1 = geluf(acc[mt][nt][half_*2+1] + bias[c0+1]);
          *(__half2*)(Cb + (long long)r*ldc + c0) = __floats2half2_rn(a0, a1);
        }
      }
    }
  } else if (ep == 4){
    float* Cb = (float*)C;
    #pragma unroll
    for (int mt = 0; mt < MTS; mt++){
      int r0 = (int)(bm + wr + mt*16 + g);
      #pragma unroll
      for (int half_ = 0; half_ < 2; half_++){
        int r = r0 + half_*8;
        int isT = (r < MT);
        int bb = isT ? (r/LT) : ((r-MT)/NI);
        const float* gate = (isT ? epEt : epEi) + bb*E6 + go;
        const float* bias = isT ? epBt : epBi;
        const float* Cur = epRt + (long long)r*DM;
        #pragma unroll
        for (int nt = 0; nt < 4; nt++){
          int c0 = (int)(bn + wc + nt*8 + 2*tg);
          float a0 = acc[mt][nt][half_*2+0] + bias[c0];
          float a1 = acc[mt][nt][half_*2+1] + bias[c0+1];
          float2 o = make_float2(Cur[c0] + gate[c0]*a0, Cur[c0+1] + gate[c0+1]*a1);
          *(float2*)(Cb + (long long)r*ldc + c0) = o;
        }
      }
    }
  } else {
    // ep == 5: QKV scatter
    int typ = (int)(bn >> 9);
    int hh2 = ((int)bn >> 7) & 3;
    #pragma unroll
    for (int mt = 0; mt < MTS; mt++){
      #pragma unroll
      for (int half_ = 0; half_ < 2; half_++){
        int r = (int)bm + wr + mt*16 + g + half_*8;
        int isT = (r < MT);
        int bidx, kv, n = 0;
        if (isT){ bidx = r >> 9; kv = r & (LT-1); }
        else { int rr = r - MT; bidx = rr >> 11; n = rr & (NI-1); kv = LT + n; }
        long long zz = (long long)(bidx*NHD + hh2);
        if (typ == 2){
          #pragma unroll
          for (int nt = 0; nt < 4; nt++){
            int cl = wc + nt*8 + 2*tg;
            Vp[(zz*HDD + cl  )*KVL + kv] = __float2half_rn(acc[mt][nt][half_*2+0]);
            Vp[(zz*HDD + cl+1)*KVL + kv] = __float2half_rn(acc[mt][nt][half_*2+1]);
          }
        } else {
          __half* dst = (typ == 0 ? Qp : Kp) + (zz*KVL + kv)*HDD;
          if (isT){
            #pragma unroll
            for (int nt = 0; nt < 4; nt++){
              int cl = wc + nt*8 + 2*tg;
              *(__half2*)(dst + cl) = __floats2half2_rn(acc[mt][nt][half_*2+0], acc[mt][nt][half_*2+1]);
            }
          } else {
            float m = modp[zz*NI + n];
            #pragma unroll
            for (int nt = 0; nt < 4; nt++){
              int cl = wc + nt*8 + 2*tg;
              float c = ropep[n*HDD + cl];
              float s = ropep[n*HDD + cl + 1];
              float a0 = acc[mt][nt][half_*2+0];
              float a1 = acc[mt][nt][half_*2+1];
              *(__half2*)(dst + cl) = __floats2half2_rn((a0*c - a1*s)*m, (a1*c + a0*s)*m);
            }
          }
        }
      }
    }
  }
}

#define TG_DSMEM4 ((2*(128*TSH) + 2*STAGE_B_H)*2)   // 73728
#define TG_DSMEM2 ((2*(64*TSH)  + 2*STAGE_B_H)*2)   // 55296

// ================= fused flash attention (base-2 softmax, Q-region reuse) =================
#define QT 64
#define KT 64
#define NKT (KVL/KT)
#define QSTR 136
#define VSTR 72
#define FL_STG (KT*QSTR + HDD*VSTR)
#define FL_DSMEM (2*FL_STG*2)

__global__ __launch_bounds__(128, 3) void k_flash(
    const __half* __restrict__ Q, const __half* __restrict__ K,
    const __half* __restrict__ V,
    __half* __restrict__ ap, const float* __restrict__ eff)
{
  extern __shared__ __half sm[];

  const int tid = threadIdx.x;
  const int lw  = tid & 31;
  const int w   = tid >> 5;
  const int g   = lw >> 2;
  const int tg  = lw & 3;
  const int qt  = blockIdx.x;
  const int z   = blockIdx.y;
  const int b   = z >> 2;
  const int h   = z & 3;
  const float alpha = ((qt < LT/QT) ? SCALE_C : eff[b]) * LOG2E;

  const __half* Qg = Q + (long long)z*KVL*HDD + (long long)qt*QT*HDD;
  const __half* Kg = K + (long long)z*KVL*HDD;
  const __half* Vg = V + (long long)z*HDD*KVL;

  auto load_tile = [&](int t, int st){
    __half* sk = sm + st*FL_STG;
    __half* sv = sk + KT*QSTR;
    int row = tid >> 1;
    int co  = (tid & 1) * 64;
    uint32_t dk = sptr(sk + row*QSTR + co);
    const __half* ks = Kg + (long long)(t*KT + row)*HDD + co;
    #pragma unroll
    for (int j = 0; j < 8; j++) CPA16(dk + j*16, ks + j*8);
    uint32_t dv = sptr(sv + tid*VSTR);
    const __half* vs = Vg + (long long)tid*KVL + t*KT;
    #pragma unroll
    for (int j = 0; j < 8; j++) CPA16(dv + j*16, vs + j*8);
    asm volatile("cp.async.commit_group;");
  };

  {
    int row = tid >> 1;
    int co  = (tid & 1) * 64;
    uint32_t dq = sptr(sm + row*QSTR + co);
    const __half* src = Qg + (long long)row*HDD + co;
    #pragma unroll
    for (int j = 0; j < 8; j++) CPA16(dq + j*16, src + j*8);
    asm volatile("cp.async.commit_group;");
  }
  load_tile(0, 1);
  asm volatile("cp.async.wait_group 0;" ::: "memory");
  __syncthreads();

  const int a_row = lw & 15;
  const int a_kh  = (lw >> 4) * 8;
  const int b_row = (lw & 7) + ((lw >> 4) & 1) * 8;
  const int b_kh  = ((lw >> 3) & 1) * 8;

  uint32_t aq[8][4];
  {
    const uint32_t sqb = sptr(sm);
    #pragma unroll
    for (int s = 0; s < 8; s++)
      LDMX4(aq[s][0], aq[s][1], aq[s][2], aq[s][3],
            sqb + (uint32_t)(((w*16 + a_row)*QSTR + s*16 + a_kh) * 2));
  }
  __syncthreads();

  float O[16][4];
  #pragma unroll
  for (int i=0;i<16;i++){ O[i][0]=0.f; O[i][1]=0.f; O[i][2]=0.f; O[i][3]=0.f; }
  float m0 = -1e30f, m1 = -1e30f, l0 = 0.f, l1 = 0.f;

  for (int t = 0; t < NKT; t++){
    int cur = (t + 1) & 1;
    if (t + 1 < NKT){
      load_tile(t+1, t & 1);
      asm volatile("cp.async.wait_group 1;" ::: "memory");
    } else {
      asm volatile("cp.async.wait_group 0;" ::: "memory");
    }
    __syncthreads();

    uint32_t skb = sptr(sm) + (uint32_t)(cur*FL_STG*2);
    uint32_t svb = skb + KT*QSTR*2;

    float sacc[8][4];
    #pragma unroll
    for (int i=0;i<8;i++){ sacc[i][0]=0.f; sacc[i][1]=0.f; sacc[i][2]=0.f; sacc[i][3]=0.f; }
    #pragma unroll
    for (int s = 0; s < 8; s++){
      uint32_t bk[8][2];
      #pragma unroll
      for (int p = 0; p < 4; p++)
        LDMX4(bk[p*2][0], bk[p*2][1], bk[p*2+1][0], bk[p*2+1][1],
              skb + (uint32_t)(((p*16 + b_row)*QSTR + s*16 + b_kh) * 2));
      #pragma unroll
      for (int nt = 0; nt < 8; nt++)
        HMMA(sacc[nt], aq[s], bk[nt]);
    }

    float mx0 = -1e30f, mx1 = -1e30f;
    #pragma unroll
    for (int nt = 0; nt < 8; nt++){
      sacc[nt][0] *= alpha; sacc[nt][1] *= alpha;
      sacc[nt][2] *= alpha; sacc[nt][3] *= alpha;
      mx0 = fmaxf(mx0, fmaxf(sacc[nt][0], sacc[nt][1]));
      mx1 = fmaxf(mx1, fmaxf(sacc[nt][2], sacc[nt][3]));
    }
    mx0 = fmaxf(mx0, __shfl_xor_sync(0xffffffffu, mx0, 1));
    mx0 = fmaxf(mx0, __shfl_xor_sync(0xffffffffu, mx0, 2));
    mx1 = fmaxf(mx1, __shfl_xor_sync(0xffffffffu, mx1, 1));
    mx1 = fmaxf(mx1, __shfl_xor_sync(0xffffffffu, mx1, 2));
    float mn0 = fmaxf(m0, mx0), mn1 = fmaxf(m1, mx1);
    float c0 = exp2f(m0 - mn0), c1 = exp2f(m1 - mn1);
    float sum0 = 0.f, sum1 = 0.f;
    #pragma unroll
    for (int nt = 0; nt < 8; nt++){
      sacc[nt][0] = exp2f(sacc[nt][0] - mn0);
      sacc[nt][1] = exp2f(sacc[nt][1] - mn0);
      sacc[nt][2] = exp2f(sacc[nt][2] - mn1);
      sacc[nt][3] = exp2f(sacc[nt][3] - mn1);
      sum0 += sacc[nt][0] + sacc[nt][1];
      sum1 += sacc[nt][2] + sacc[nt][3];
    }
    sum0 += __shfl_xor_sync(0xffffffffu, sum0, 1);
    sum0 += __shfl_xor_sync(0xffffffffu, sum0, 2);
    sum1 += __shfl_xor_sync(0xffffffffu, sum1, 1);
    sum1 += __shfl_xor_sync(0xffffffffu, sum1, 2);
    l0 = l0*c0 + sum0;  l1 = l1*c1 + sum1;
    m0 = mn0;  m1 = mn1;
    #pragma unroll
    for (int nt = 0; nt < 16; nt++){
      O[nt][0] *= c0; O[nt][1] *= c0;
      O[nt][2] *= c1; O[nt][3] *= c1;
    }

    uint32_t pf[4][4];
    #pragma unroll
    for (int j = 0; j < 4; j++){
      __half2 h0 = __floats2half2_rn(sacc[2*j][0],   sacc[2*j][1]);
      __half2 h1 = __floats2half2_rn(sacc[2*j][2],   sacc[2*j][3]);
      __half2 h2 = __floats2half2_rn(sacc[2*j+1][0], sacc[2*j+1][1]);
      __half2 h3 = __floats2half2_rn(sacc[2*j+1][2], sacc[2*j+1][3]);
      pf[j][0] = *(uint32_t*)&h0;  pf[j][1] = *(uint32_t*)&h1;
      pf[j][2] = *(uint32_t*)&h2;  pf[j][3] = *(uint32_t*)&h3;
    }

    #pragma unroll
    for (int s = 0; s < 4; s++){
      uint32_t bv[16][2];
      #pragma unroll
      for (int p = 0; p < 8; p++)
        LDMX4(bv[p*2][0], bv[p*2][1], bv[p*2+1][0], bv[p*2+1][1],
              svb + (uint32_t)(((p*16 + b_row)*VSTR + s*16 + b_kh) * 2));
      #pragma unroll
      for (int nt = 0; nt < 16; nt++)
        HMMA(O[nt], pf[s], bv[nt]);
    }
    __syncthreads();
  }

  float i0 = 1.f/l0, i1 = 1.f/l1;
  int q0 = qt*QT + w*16 + g;
  int q1 = q0 + 8;
  long long tok0 = (q0 < LT) ? (long long)(b*LT + q0) : (long long)(MT + b*NI + (q0 - LT));
  long long tok1 = (q1 < LT) ? (long long)(b*LT + q1) : (long long)(MT + b*NI + (q1 - LT));
  __half* o0 = ap + tok0*DM + h*HDD + 2*tg;
  __half* o1 = ap + tok1*DM + h*HDD + 2*tg;
  #pragma unroll
  for (int nt = 0; nt < 16; nt++){
    *(__half2*)(o0 + nt*8) = __floats2half2_rn(O[nt][0]*i0, O[nt][1]*i0);
    *(__half2*)(o1 + nt*8) = __floats2half2_rn(O[nt][2]*i1, O[nt][3]*i1);
  }
}

// ---------------- fused prologue: emb + mod + eff + weight->half (one launch) ----------------
__global__ void k_prep(const float* __restrict__ vec,
                       const float* __restrict__ Wi, const float* __restrict__ bi_,
                       const float* __restrict__ Wt, const float* __restrict__ bt_,
                       float* __restrict__ ei, float* __restrict__ et,
                       const float* __restrict__ sp, const float* __restrict__ mw,
                       const float* __restrict__ mb, float* __restrict__ mod,
                       const float* __restrict__ temp, float* __restrict__ eff,
                       const float* __restrict__ c0, __half* __restrict__ o0,
                       const float* __restrict__ c1, __half* __restrict__ o1,
                       const float* __restrict__ c2, __half* __restrict__ o2,
                       const float* __restrict__ c3, __half* __restrict__ o3,
                       const float* __restrict__ c4, __half* __restrict__ o4,
                       const float* __restrict__ c5, __half* __restrict__ o5,
                       const float* __restrict__ c6, __half* __restrict__ o6,
                       const float* __restrict__ c7, __half* __restrict__ o7)
{
  int blk = blockIdx.x;
  if (blk < 64){
    if (blk == 0 && threadIdx.x < NB){
      int b = threadIdx.x;
      float m = 0.25f*(temp[b*NHD+0]+temp[b*NHD+1]+temp[b*NHD+2]+temp[b*NHD+3]);
      eff[b] = SCALE_C / fmaxf(m, 0.1f);
    }
    int idx = blk*256 + threadIdx.x;
    int n = idx & (NI-1);
    int h = (idx >> 11) & (NHD-1);
    int b = idx >> 13;
    int y = n >> 5;
    int x = n & 31;
    float fy = (y + 0.5f)*0.125f - 0.5f;
    float fx = (x + 0.5f)*0.25f  - 0.5f;
    int y0 = (int)floorf(fy); float wy = fy - (float)y0;
    int x0 = (int)floorf(fx); float wx = fx - (float)x0;
    int y0c = min(max(y0,0),7), y1c = min(max(y0+1,0),7);
    int x0c = min(max(x0,0),7), x1c = min(max(x0+1,0),7);
    const float* p = sp + b*64;
    float v = (1.f-wy)*((1.f-wx)*p[y0c*8+x0c] + wx*p[y0c*8+x1c])
            +      wy *((1.f-wx)*p[y1c*8+x0c] + wx*p[y1c*8+x1c]);
    v = v*mw[h] + mb[h];
    v = fminf(fmaxf(v, -2.f), 2.f);
    mod[idx] = expf(v);
  } else if (blk < 112){
    int be = blk - 64;
    int xb = be % 12;
    int b  = (be / 12) & 1;
    int zi = be / 24;
    const float* W  = zi ? Wt  : Wi;
    const float* bs = zi ? bt_ : bi_;
    float* e        = zi ? et  : ei;
    __shared__ float s[DM];
    for (int i = threadIdx.x; i < DM; i += blockDim.x){
      float v = vec[b*DM + i];
      s[i] = v / (1.f + expf(-v));
    }
    __syncthreads();
    int n = xb*256 + threadIdx.x;
    const float* wr = W + (long long)n*DM;
    float acc = 0.f;
    #pragma unroll 8
    for (int k = 0; k < DM; k++) acc += s[k]*wr[k];
    e[b*E6 + n] = acc + bs[n];
  } else {
    int idx = (blk - 112)*256 + threadIdx.x;   // float4 index, total 1572864
    const float4* in; __half2* out; int off;
    if      (idx <  196608){ in=(const float4*)c0; out=(__half2*)o0; off=0; }
    else if (idx <  393216){ in=(const float4*)c1; out=(__half2*)o1; off=196608; }
    else if (idx <  458752){ in=(const float4*)c2; out=(__half2*)o2; off=393216; }
    else if (idx <  524288){ in=(const float4*)c3; out=(__half2*)o3; off=458752; }
    else if (idx <  786432){ in=(const float4*)c4; out=(__half2*)o4; off=524288; }
    else if (idx < 1048576){ in=(const float4*)c5; out=(__half2*)o5; off=786432; }
    else if (idx < 1310720){ in=(const float4*)c6; out=(__half2*)o6; off=1048576; }
    else                   { in=(const float4*)c7; out=(__half2*)o7; off=1310720; }
    int j = idx - off;
    float4 v = in[j];
    out[j*2]   = __floats2half2_rn(v.x, v.y);
    out[j*2+1] = __floats2half2_rn(v.z, v.w);
  }
}

// ---------------- combined rms-norm + adaln modulate -> half ----------------
__global__ __launch_bounds__(128) void k_rmsmod(
    const float* __restrict__ xt, const float* __restrict__ xi,
    const float* __restrict__ wt, const float* __restrict__ wi,
    const float* __restrict__ et, const float* __restrict__ ei,
    int shift_off, int scale_off, __half* __restrict__ out)
{
  int row = blockIdx.x;
  const float* x; const float* w; const float* eb;
  if (row < MT){
    x = xt + (long long)row*DM; w = wt; eb = et + (row/LT)*E6;
  } else {
    int rr = row - MT;
    x = xi + (long long)rr*DM; w = wi; eb = ei + (rr/NI)*E6;
  }
  float4 xv = ((const float4*)x)[threadIdx.x];
  float ss = xv.x*xv.x + xv.y*xv.y + xv.z*xv.z + xv.w*xv.w;
  ss = warpSum(ss);
  __shared__ float red[4];
  int lane = threadIdx.x & 31, wid = threadIdx.x >> 5;
  if (lane==0) red[wid]=ss;
  __syncthreads();
  float tot = red[0]+red[1]+red[2]+red[3];
  float inv = rsqrtf(tot*(1.f/DM) + 1e-6f);
  int c = threadIdx.x*4;
  float ox = xv.x*inv*w[c+0]*(1.f+eb[scale_off+c+0]) + eb[shift_off+c+0];
  float oy = xv.y*inv*w[c+1]*(1.f+eb[scale_off+c+1]) + eb[shift_off+c+1];
  float oz = xv.z*inv*w[c+2]*(1.f+eb[scale_off+c+2]) + eb[shift_off+c+2];
  float ow = xv.w*inv*w[c+3]*(1.f+eb[scale_off+c+3]) + eb[shift_off+c+3];
  __half2* op = (__half2*)(out + (long long)row*DM);
  op[threadIdx.x*2]   = __floats2half2_rn(ox, oy);
  op[threadIdx.x*2+1] = __floats2half2_rn(oz, ow);
}

// ---------------- launch ----------------
#define GETSYMF(var, sym) float* var; cudaGetSymbolAddress((void**)&var, sym)
#define GETSYMH(var, sym) __half* var; cudaGetSymbolAddress((void**)&var, sym)

extern "C" void kernel_launch(void* const* d_in, const int* in_sizes, int n_in,
                              void* d_out, int out_size)
{
  const float* txt          = (const float*)d_in[0];
  const float* img          = (const float*)d_in[1];
  const float* vec          = (const float*)d_in[2];
  const float* rope         = (const float*)d_in[3];
  const float* sol_t        = (const float*)d_in[4];
  const float* sol_s        = (const float*)d_in[5];
  const float* img_adaln_w  = (const float*)d_in[6];
  const float* img_adaln_b  = (const float*)d_in[7];
  const float* img_adaln_nw = (const float*)d_in[8];
  const float* txt_adaln_w  = (const float*)d_in[9];
  const float* txt_adaln_b  = (const float*)d_in[10];
  const float* txt_adaln_nw = (const float*)d_in[11];
  const float* txt_qkv_w    = (const float*)d_in[12];
  const float* img_qkv_w    = (const float*)d_in[13];
  const float* txt_out_w    = (const float*)d_in[14];
  const float* img_out_w    = (const float*)d_in[15];
  const float* sol_mod_w    = (const float*)d_in[16];
  const float* sol_mod_b    = (const float*)d_in[17];
  const float* img_norm2_w  = (const float*)d_in[18];
  const float* txt_norm2_w  = (const float*)d_in[19];
  const float* img_fc1_w    = (const float*)d_in[20];
  const float* img_fc1_b    = (const float*)d_in[21];
  const float* img_fc2_w    = (const float*)d_in[22];
  const float* img_fc2_b    = (const float*)d_in[23];
  const float* txt_fc1_w    = (const float*)d_in[24];
  const float* txt_fc1_b    = (const float*)d_in[25];
  const float* txt_fc2_w    = (const float*)d_in[26];
  const float* txt_fc2_b    = (const float*)d_in[27];
  float* out = (float*)d_out;

  GETSYMF(e_img, d_e_img);  GETSYMF(e_txt, d_e_txt);
  GETSYMF(eff, d_eff);      GETSYMF(mod, d_mod);
  GETSYMH(nrm, d_nrm);
  GETSYMH(Qc, d_Qc);        GETSYMH(Kc, d_Kc);
  GETSYMH(VT, d_VT);
  GETSYMH(ap, d_ap);        GETSYMH(hh, d_h);
  GETSYMF(cc, d_c);
  GETSYMH(wq_t, d_wq_t);    GETSYMH(wq_i, d_wq_i);
  GETSYMH(wo_t, d_wo_t);    GETSYMH(wo_i, d_wo_i);
  GETSYMH(w1_t, d_w1_t);    GETSYMH(w1_i, d_w1_i);
  GETSYMH(w2_t, d_w2_t);    GETSYMH(w2_i, d_w2_i);

  cudaFuncSetAttribute((const void*)tgemm<4,1>, cudaFuncAttributeMaxDynamicSharedMemorySize, TG_DSMEM4);
  cudaFuncSetAttribute((const void*)tgemm<2,4>, cudaFuncAttributeMaxDynamicSharedMemorySize, TG_DSMEM2);
  cudaFuncSetAttribute((const void*)k_flash,    cudaFuncAttributeMaxDynamicSharedMemorySize, FL_DSMEM);

  // 1. fused prologue (emb + mod + eff + weights->half)
  k_prep<<<112 + 6144, 256>>>(vec, img_adaln_w, img_adaln_b, txt_adaln_w, txt_adaln_b,
                              e_img, e_txt, sol_s, sol_mod_w, sol_mod_b, mod, sol_t, eff,
                              txt_qkv_w, wq_t, img_qkv_w, wq_i,
                              txt_out_w, wo_t, img_out_w, wo_i,
                              txt_fc1_w, w1_t, img_fc1_w, w1_i,
                              txt_fc2_w, w2_t, img_fc2_w, w2_i);
  // 2. norm1 combined -> half
  k_rmsmod<<<MALL, 128>>>(txt, img, txt_adaln_nw, img_adaln_nw, e_txt, e_img, 0, 512, nrm);
  // 3. QKV GEMM (64-row tiles, ep5 scatter) -> Qc, Kc, VT
  tgemm<2,4><<<dim3(12, MALL/64, 1), 256, TG_DSMEM2>>>(nrm, wq_t, wq_i, MT,
      Qc, 1536, DM, 1536, 0, 0,
      BIGR, 1, 0, 0, 0, 0, 1.f, eff, 1, BIGR,
      5, nullptr, nullptr, nullptr, nullptr, nullptr, nullptr, 0,
      rope, mod, Qc, Kc, VT);
  // 4. fused flash attention -> packed half ap   [profiled launch #4]
  k_flash<<<dim3(KVL/QT, NB*NHD), 128, FL_DSMEM>>>(Qc, Kc, VT, ap, eff);
  // 5. output projection + residual gate (ep2) -> float cc
  tgemm<2,4><<<dim3(4, MALL/64, 1), 256, TG_DSMEM2>>>(ap, wo_t, wo_i, MT,
      cc, DM, DM, DM, 0, 0,
      BIGR, 1, 0, 0, 0, 0, 1.f, eff, 1, BIGR,
      2, txt, img, e_txt, e_img, nullptr, nullptr, 1024,
      nullptr, nullptr, nullptr, nullptr, nullptr);
  // 6. norm2 combined -> half
  k_rmsmod<<<MALL, 128>>>(cc, cc + (long long)MT*DM, txt_norm2_w, img_norm2_w,
                          e_txt, e_img, 1536, 2048, nrm);
  // 7. fc1 + bias + gelu (ep3) -> half h
  tgemm<4,1><<<dim3(16, MALL/128, 1), 256, TG_DSMEM4>>>(nrm, w1_t, w1_i, MT,
      hh, FFD, DM, FFD, 0, 0,
      BIGR, 1, 0, 0, 0, 0, 1.f, eff, 1, BIGR,
      3, nullptr, nullptr, nullptr, nullptr, txt_fc1_b, img_fc1_b, 0,
      nullptr, nullptr, nullptr, nullptr, nullptr);
  // 8. fc2 + bias + gate + residual (ep4) -> d_out
  tgemm<2,4><<<dim3(4, MALL/64, 1), 256, TG_DSMEM2>>>(hh, w2_t, w2_i, MT,
      out, DM, FFD, DM, 0, 0,
      BIGR, 1, 0, 0, 0, 0, 1.f, eff, 1, BIGR,
      4, cc, nullptr, e_txt, e_img, txt_fc2_b, img_fc2_b, 2560,
      nullptr, nullptr, nullptr, nullptr, nullptr);
}

// round 16
// speedup vs baseline: 1.0605x; 1.0605x over previous
#include <cuda_runtime.h>
#include <cuda_fp16.h>
#include <math.h>
#include <stdint.h>

// ---------------- problem dims (fixed) ----------------
#define NB   2
#define LT   512
#define NI   2048
#define DM   512
#define NHD  4
#define HDD  128
#define FFD  2048
#define KVL  2560
#define E6   3072
#define MT   (NB*LT)
#define MI   (NB*NI)
#define MALL (MT+MI)
#define NZ   (NB*NHD)
#define SCALE_C 0.08838834764831845f
#define LOG2E 1.44269504f
#define BIGR (1<<30)

// ---------------- scratch ----------------
__device__ __align__(256) float  d_e_img[NB*E6];
__device__ __align__(256) float  d_e_txt[NB*E6];
__device__ __align__(256) float  d_eff[NB];
__device__ __align__(256) float  d_mod[NB*NHD*NI];
__device__ __align__(256) __half d_nrm[MALL*DM];
__device__ __align__(256) __half d_Qc[NZ*KVL*HDD];
__device__ __align__(256) __half d_Kc[NZ*KVL*HDD];
__device__ __align__(256) __half d_VT[NZ*HDD*KVL];
__device__ __align__(256) __half d_ap[MALL*DM];
__device__ __align__(256) __half d_h[MALL*FFD];
__device__ __align__(256) float  d_c[MALL*DM];
__device__ __align__(256) float  d_Op[2*NZ*KVL*HDD];   // split-KV partial O
__device__ __align__(256) float2 d_ml[2*NZ*KVL];       // split-KV partial (m, l)
// half weights
__device__ __align__(256) __half d_wq_t[1536*DM];
__device__ __align__(256) __half d_wq_i[1536*DM];
__device__ __align__(256) __half d_wo_t[DM*DM];
__device__ __align__(256) __half d_wo_i[DM*DM];
__device__ __align__(256) __half d_w1_t[FFD*DM];
__device__ __align__(256) __half d_w1_i[FFD*DM];
__device__ __align__(256) __half d_w2_t[DM*FFD];
__device__ __align__(256) __half d_w2_i[DM*FFD];

// ---------------- helpers ----------------
__device__ __forceinline__ float warpSum(float v){
  #pragma unroll
  for (int o=16;o>0;o>>=1) v += __shfl_xor_sync(0xffffffffu, v, o);
  return v;
}
__device__ __forceinline__ uint32_t sptr(const void* p){
  uint32_t r;
  asm("{ .reg .u64 t; cvta.to.shared.u64 t, %1; cvt.u32.u64 %0, t; }" : "=r"(r) : "l"(p));
  return r;
}
__device__ __forceinline__ float geluf(float x){
  float t = tanhf(0.7978845608028654f*(x + 0.044715f*x*x*x));
  return 0.5f*x*(1.f+t);
}
#define HMMA(acc, a, b) \
  asm volatile( \
    "mma.sync.aligned.m16n8k16.row.col.f32.f16.f16.f32 " \
    "{%0,%1,%2,%3}, {%4,%5,%6,%7}, {%8,%9}, {%0,%1,%2,%3};" \
    : "+f"((acc)[0]), "+f"((acc)[1]), "+f"((acc)[2]), "+f"((acc)[3]) \
    : "r"((a)[0]), "r"((a)[1]), "r"((a)[2]), "r"((a)[3]), \
      "r"((b)[0]), "r"((b)[1]))
#define LDMX4(r0,r1,r2,r3, addr) \
  asm volatile("ldmatrix.sync.aligned.m8n8.x4.shared.b16 {%0,%1,%2,%3}, [%4];" \
    : "=r"(r0), "=r"(r1), "=r"(r2), "=r"(r3) : "r"(addr))
#define CPA16(dst, src) \
  asm volatile("cp.async.cg.shared.global [%0], [%1], 16;" :: "r"(dst), "l"(src))

// ================= fp16 mma.sync batched GEMM, K-chunk 64, fused epilogues =================
#define TSH 72
#define STAGE_B_H (128*TSH)

template<int MTS>
__global__ __launch_bounds__(256) void tgemm(
    const __half* __restrict__ A, const __half* __restrict__ B1,
    const __half* __restrict__ B2, int msplit,
    void* __restrict__ C, int N, int K, int ldc,
    long long sA, long long sB,
    int rsplit, int zdiv, long long sCt, long long sCi, long long sCh, long long cbase,
    float alpha, const float* __restrict__ alphas, int adiv, int arsplit,
    int ep,
    const float* __restrict__ epRt, const float* __restrict__ epRi,
    const float* __restrict__ epEt, const float* __restrict__ epEi,
    const float* __restrict__ epBt, const float* __restrict__ epBi, int go,
    const float* __restrict__ ropep, const float* __restrict__ modp,
    __half* __restrict__ Qp, __half* __restrict__ Kp, __half* __restrict__ Vp)
{
  constexpr int CTAM = MTS*32;
  constexpr int STAGE_A_H = CTAM*TSH;
  extern __shared__ __half smh[];
  __half* As = smh;
  __half* Bs = smh + 2*STAGE_A_H;

  const int tid = threadIdx.x;
  const int z   = blockIdx.z;
  const long long bm = (long long)blockIdx.y * CTAM;
  const long long bn = (long long)blockIdx.x * 128;

  const __half* Ab = A + z*sA + bm*K;
  const __half* Bsel = (bm < msplit) ? B1 : B2;
  const __half* Bb = Bsel + z*sB + bn*K;

  float alp = ((int)bm < arsplit) ? alpha : alphas[z/adiv];
  long long zoff = ((int)bm < rsplit)
      ? (long long)(z/zdiv)*sCt + (long long)(z%zdiv)*sCh
      : cbase + (long long)(z/zdiv)*sCi + (long long)(z%zdiv)*sCh;

  const int lw  = tid & 31;
  const int w   = tid >> 5;
  const int wr  = (w >> 2) * (MTS*16);
  const int wc  = (w & 3) * 32;
  const int g   = lw >> 2;
  const int tg  = lw & 3;

  constexpr int ASH  = (MTS == 4) ? 1 : 2;
  constexpr int ANSEG = (MTS == 4) ? 4 : 2;
  const int a_lrow = tid >> ASH;
  const int a_lsel = (tid & ((1<<ASH)-1)) * (ANSEG*8);
  const int b_lrow = tid >> 1;
  const int b_lsel = (tid & 1) * 32;

  const int a_row = lw & 15;
  const int a_kh  = (lw >> 4) * 8;
  uint32_t aoff[MTS];
  #pragma unroll
  for (int mt = 0; mt < MTS; mt++)
    aoff[mt] = (uint32_t)(((wr + mt*16 + a_row)*TSH + a_kh) * 2);
  const int b_row = (lw & 7) + ((lw >> 4) & 1) * 8;
  const int b_kh  = ((lw >> 3) & 1) * 8;
  uint32_t boff[2];
  #pragma unroll
  for (int n2 = 0; n2 < 2; n2++)
    boff[n2] = (uint32_t)(((wc + n2*16 + b_row)*TSH + b_kh) * 2);

  const uint32_t Abase = sptr(As);
  const uint32_t Bbase = sptr(Bs);

  float acc[MTS][4][4];
  #pragma unroll
  for (int i=0;i<MTS;i++)
    #pragma unroll
    for (int j=0;j<4;j++)
      #pragma unroll
      for (int q=0;q<4;q++) acc[i][j][q] = 0.f;

  const int nch = K >> 6;

  auto load_chunk = [&](int c, int st){
    const __half* Ag = Ab + (long long)a_lrow*K + c*64 + a_lsel;
    uint32_t da = sptr(As + st*STAGE_A_H + a_lrow*TSH + a_lsel);
    #pragma unroll
    for (int j = 0; j < ANSEG; j++) CPA16(da + j*16, Ag + j*8);
    const __half* Bg = Bb + (long long)b_lrow*K + c*64 + b_lsel;
    uint32_t db = sptr(Bs + st*STAGE_B_H + b_lrow*TSH + b_lsel);
    #pragma unroll
    for (int j = 0; j < 4; j++) CPA16(db + j*16, Bg + j*8);
    asm volatile("cp.async.commit_group;");
  };

  load_chunk(0, 0);

  for (int i = 0; i < nch; i++){
    int st = i & 1;
    if (i + 1 < nch){
      load_chunk(i+1, st^1);
      asm volatile("cp.async.wait_group 1;" ::: "memory");
    } else {
      asm volatile("cp.async.wait_group 0;" ::: "memory");
    }
    __syncthreads();

    uint32_t sa = Abase + st*STAGE_A_H*2;
    uint32_t sb = Bbase + st*STAGE_B_H*2;

    #pragma unroll
    for (int ks = 0; ks < 4; ks++){
      uint32_t koff = ks*32;
      uint32_t af[MTS][4];
      #pragma unroll
      for (int mt = 0; mt < MTS; mt++)
        LDMX4(af[mt][0], af[mt][1], af[mt][2], af[mt][3], sa + aoff[mt] + koff);
      uint32_t bf[4][2];
      #pragma unroll
      for (int n2 = 0; n2 < 2; n2++)
        LDMX4(bf[n2*2][0], bf[n2*2][1], bf[n2*2+1][0], bf[n2*2+1][1], sb + boff[n2] + koff);
      #pragma unroll
      for (int mt = 0; mt < MTS; mt++)
        #pragma unroll
        for (int nt = 0; nt < 4; nt++)
          HMMA(acc[mt][nt], af[mt], bf[nt]);
    }
    __syncthreads();
  }

  // -------- epilogue --------
  if (ep == 1){
    __half* Cb = (__half*)C + zoff;
    #pragma unroll
    for (int mt = 0; mt < MTS; mt++){
      long long r0 = bm + wr + mt*16 + g;
      #pragma unroll
      for (int nt = 0; nt < 4; nt++){
        long long c0 = bn + wc + nt*8 + 2*tg;
        *(__half2*)(Cb + r0*ldc + c0)     = __floats2half2_rn(acc[mt][nt][0]*alp, acc[mt][nt][1]*alp);
        *(__half2*)(Cb + (r0+8)*ldc + c0) = __floats2half2_rn(acc[mt][nt][2]*alp, acc[mt][nt][3]*alp);
      }
    }
  } else if (ep == 0){
    float* Cb = (float*)C + zoff;
    #pragma unroll
    for (int mt = 0; mt < MTS; mt++){
      long long r0 = bm + wr + mt*16 + g;
      #pragma unroll
      for (int nt = 0; nt < 4; nt++){
        long long c0 = bn + wc + nt*8 + 2*tg;
        *(float2*)(Cb + r0*ldc + c0)     = make_float2(acc[mt][nt][0]*alp, acc[mt][nt][1]*alp);
        *(float2*)(Cb + (r0+8)*ldc + c0) = make_float2(acc[mt][nt][2]*alp, acc[mt][nt][3]*alp);
      }
    }
  } else if (ep == 2){
    float* Cb = (float*)C;
    #pragma unroll
    for (int mt = 0; mt < MTS; mt++){
      int r0 = (int)(bm + wr + mt*16 + g);
      #pragma unroll
      for (int half_ = 0; half_ < 2; half_++){
        int r = r0 + half_*8;
        int isT = (r < MT);
        int bb = isT ? (r/LT) : ((r-MT)/NI);
        const float* gate = (isT ? epEt : epEi) + bb*E6 + go;
        const float* R = isT ? (epRt + (long long)r*DM) : (epRi + (long long)(r-MT)*DM);
        #pragma unroll
        for (int nt = 0; nt < 4; nt++){
          int c0 = (int)(bn + wc + nt*8 + 2*tg);
          float a0 = acc[mt][nt][half_*2+0], a1 = acc[mt][nt][half_*2+1];
          float2 o = make_float2(R[c0] + gate[c0]*a0, R[c0+1] + gate[c0+1]*a1);
          *(float2*)(Cb + (long long)r*ldc + c0) = o;
        }
      }
    }
  } else if (ep == 3){
    __half* Cb = (__half*)C;
    #pragma unroll
    for (int mt = 0; mt < MTS; mt++){
      int r0 = (int)(bm + wr + mt*16 + g);
      #pragma unroll
      for (int half_ = 0; half_ < 2; half_++){
        int r = r0 + half_*8;
        const float* bias = (r < MT) ? epBt : epBi;
        #pragma unroll
        for (int nt = 0; nt < 4; nt++){
          int c0 = (int)(bn + wc + nt*8 + 2*tg);
          float a0 = geluf(acc[mt][nt][half_*2+0] + bias[c0]);
          float a1 = geluf(acc[mt][nt][half_*2+1] + bias[c0+1]);
          *(__half2*)(Cb + (long long)r*ldc + c0) = __floats2half2_rn(a0, a1);
        }
      }
    }
  } else if (ep == 4){
    float* Cb = (float*)C;
    #pragma unroll
    for (int mt = 0; mt < MTS; mt++){
      int r0 = (int)(bm + wr + mt*16 + g);
      #pragma unroll
      for (int half_ = 0; half_ < 2; half_++){
        int r = r0 + half_*8;
        int isT = (r < MT);
        int bb = isT ? (r/LT) : ((r-MT)/NI);
        const float* gate = (isT ? epEt : epEi) + bb*E6 + go;
        const float* bias = isT ? epBt : epBi;
        const float* Cur = epRt + (long long)r*DM;
        #pragma unroll
        for (int nt = 0; nt < 4; nt++){
          int c0 = (int)(bn + wc + nt*8 + 2*tg);
          float a0 = acc[mt][nt][half_*2+0] + bias[c0];
          float a1 = acc[mt][nt][half_*2+1] + bias[c0+1];
          float2 o = make_float2(Cur[c0] + gate[c0]*a0, Cur[c0+1] + gate[c0+1]*a1);
          *(float2*)(Cb + (long long)r*ldc + c0) = o;
        }
      }
    }
  } else {
    // ep == 5: QKV scatter
    int typ = (int)(bn >> 9);
    int hh2 = ((int)bn >> 7) & 3;
    #pragma unroll
    for (int mt = 0; mt < MTS; mt++){
      #pragma unroll
      for (int half_ = 0; half_ < 2; half_++){
        int r = (int)bm + wr + mt*16 + g + half_*8;
        int isT = (r < MT);
        int bidx, kv, n = 0;
        if (isT){ bidx = r >> 9; kv = r & (LT-1); }
        else { int rr = r - MT; bidx = rr >> 11; n = rr & (NI-1); kv = LT + n; }
        long long zz = (long long)(bidx*NHD + hh2);
        if (typ == 2){
          #pragma unroll
          for (int nt = 0; nt < 4; nt++){
            int cl = wc + nt*8 + 2*tg;
            Vp[(zz*HDD + cl  )*KVL + kv] = __float2half_rn(acc[mt][nt][half_*2+0]);
            Vp[(zz*HDD + cl+1)*KVL + kv] = __float2half_rn(acc[mt][nt][half_*2+1]);
          }
        } else {
          __half* dst = (typ == 0 ? Qp : Kp) + (zz*KVL + kv)*HDD;
          if (isT){
            #pragma unroll
            for (int nt = 0; nt < 4; nt++){
              int cl = wc + nt*8 + 2*tg;
              *(__half2*)(dst + cl) = __floats2half2_rn(acc[mt][nt][half_*2+0], acc[mt][nt][half_*2+1]);
            }
          } else {
            float m = modp[zz*NI + n];
            #pragma unroll
            for (int nt = 0; nt < 4; nt++){
              int cl = wc + nt*8 + 2*tg;
              float c = ropep[n*HDD + cl];
              float s = ropep[n*HDD + cl + 1];
              float a0 = acc[mt][nt][half_*2+0];
              float a1 = acc[mt][nt][half_*2+1];
              *(__half2*)(dst + cl) = __floats2half2_rn((a0*c - a1*s)*m, (a1*c + a0*s)*m);
            }
          }
        }
      }
    }
  }
}

#define TG_DSMEM4 ((2*(128*TSH) + 2*STAGE_B_H)*2)
#define TG_DSMEM2 ((2*(64*TSH)  + 2*STAGE_B_H)*2)

// ================= split-KV flash attention (2 splits, unnormalized partials) =================
#define QT 64
#define KT 64
#define NKT (KVL/KT)          // 40
#define TPS (NKT/2)           // 20 tiles per split
#define QSTR 136
#define VSTR 72
#define FL_STG (KT*QSTR + HDD*VSTR)
#define FL_DSMEM (2*FL_STG*2)

__global__ __launch_bounds__(128, 3) void k_flash(
    const __half* __restrict__ Q, const __half* __restrict__ K,
    const __half* __restrict__ V,
    float* __restrict__ Op, float2* __restrict__ mlp,
    const float* __restrict__ eff)
{
  extern __shared__ __half sm[];

  const int tid = threadIdx.x;
  const int lw  = tid & 31;
  const int w   = tid >> 5;
  const int g   = lw >> 2;
  const int tg  = lw & 3;
  const int qt  = blockIdx.x;
  const int z   = blockIdx.y;
  const int sp  = blockIdx.z;          // split 0/1
  const int b   = z >> 2;
  const float alpha = ((qt < LT/QT) ? SCALE_C : eff[b]) * LOG2E;
  const int t0 = sp * TPS;

  const __half* Qg = Q + (long long)z*KVL*HDD + (long long)qt*QT*HDD;
  const __half* Kg = K + (long long)z*KVL*HDD;
  const __half* Vg = V + (long long)z*HDD*KVL;

  auto load_tile = [&](int t, int st){
    __half* sk = sm + st*FL_STG;
    __half* sv = sk + KT*QSTR;
    int row = tid >> 1;
    int co  = (tid & 1) * 64;
    uint32_t dk = sptr(sk + row*QSTR + co);
    const __half* ks = Kg + (long long)(t*KT + row)*HDD + co;
    #pragma unroll
    for (int j = 0; j < 8; j++) CPA16(dk + j*16, ks + j*8);
    uint32_t dv = sptr(sv + tid*VSTR);
    const __half* vs = Vg + (long long)tid*KVL + t*KT;
    #pragma unroll
    for (int j = 0; j < 8; j++) CPA16(dv + j*16, vs + j*8);
    asm volatile("cp.async.commit_group;");
  };

  {
    int row = tid >> 1;
    int co  = (tid & 1) * 64;
    uint32_t dq = sptr(sm + row*QSTR + co);
    const __half* src = Qg + (long long)row*HDD + co;
    #pragma unroll
    for (int j = 0; j < 8; j++) CPA16(dq + j*16, src + j*8);
    asm volatile("cp.async.commit_group;");
  }
  load_tile(t0, 1);
  asm volatile("cp.async.wait_group 0;" ::: "memory");
  __syncthreads();

  const int a_row = lw & 15;
  const int a_kh  = (lw >> 4) * 8;
  const int b_row = (lw & 7) + ((lw >> 4) & 1) * 8;
  const int b_kh  = ((lw >> 3) & 1) * 8;

  uint32_t aq[8][4];
  {
    const uint32_t sqb = sptr(sm);
    #pragma unroll
    for (int s = 0; s < 8; s++)
      LDMX4(aq[s][0], aq[s][1], aq[s][2], aq[s][3],
            sqb + (uint32_t)(((w*16 + a_row)*QSTR + s*16 + a_kh) * 2));
  }
  __syncthreads();

  float O[16][4];
  #pragma unroll
  for (int i=0;i<16;i++){ O[i][0]=0.f; O[i][1]=0.f; O[i][2]=0.f; O[i][3]=0.f; }
  float m0 = -1e30f, m1 = -1e30f, l0 = 0.f, l1 = 0.f;

  for (int tt = 0; tt < TPS; tt++){
    int cur = (tt + 1) & 1;
    if (tt + 1 < TPS){
      load_tile(t0 + tt + 1, tt & 1);
      asm volatile("cp.async.wait_group 1;" ::: "memory");
    } else {
      asm volatile("cp.async.wait_group 0;" ::: "memory");
    }
    __syncthreads();

    uint32_t skb = sptr(sm) + (uint32_t)(cur*FL_STG*2);
    uint32_t svb = skb + KT*QSTR*2;

    float sacc[8][4];
    #pragma unroll
    for (int i=0;i<8;i++){ sacc[i][0]=0.f; sacc[i][1]=0.f; sacc[i][2]=0.f; sacc[i][3]=0.f; }
    #pragma unroll
    for (int s = 0; s < 8; s++){
      uint32_t bk[8][2];
      #pragma unroll
      for (int p = 0; p < 4; p++)
        LDMX4(bk[p*2][0], bk[p*2][1], bk[p*2+1][0], bk[p*2+1][1],
              skb + (uint32_t)(((p*16 + b_row)*QSTR + s*16 + b_kh) * 2));
      #pragma unroll
      for (int nt = 0; nt < 8; nt++)
        HMMA(sacc[nt], aq[s], bk[nt]);
    }

    float mx0 = -1e30f, mx1 = -1e30f;
    #pragma unroll
    for (int nt = 0; nt < 8; nt++){
      sacc[nt][0] *= alpha; sacc[nt][1] *= alpha;
      sacc[nt][2] *= alpha; sacc[nt][3] *= alpha;
      mx0 = fmaxf(mx0, fmaxf(sacc[nt][0], sacc[nt][1]));
      mx1 = fmaxf(mx1, fmaxf(sacc[nt][2], sacc[nt][3]));
    }
    mx0 = fmaxf(mx0, __shfl_xor_sync(0xffffffffu, mx0, 1));
    mx0 = fmaxf(mx0, __shfl_xor_sync(0xffffffffu, mx0, 2));
    mx1 = fmaxf(mx1, __shfl_xor_sync(0xffffffffu, mx1, 1));
    mx1 = fmaxf(mx1, __shfl_xor_sync(0xffffffffu, mx1, 2));
    float mn0 = fmaxf(m0, mx0), mn1 = fmaxf(m1, mx1);
    float c0 = exp2f(m0 - mn0), c1 = exp2f(m1 - mn1);
    float sum0 = 0.f, sum1 = 0.f;
    #pragma unroll
    for (int nt = 0; nt < 8; nt++){
      sacc[nt][0] = exp2f(sacc[nt][0] - mn0);
      sacc[nt][1] = exp2f(sacc[nt][1] - mn0);
      sacc[nt][2] = exp2f(sacc[nt][2] - mn1);
      sacc[nt][3] = exp2f(sacc[nt][3] - mn1);
      sum0 += sacc[nt][0] + sacc[nt][1];
      sum1 += sacc[nt][2] + sacc[nt][3];
    }
    sum0 += __shfl_xor_sync(0xffffffffu, sum0, 1);
    sum0 += __shfl_xor_sync(0xffffffffu, sum0, 2);
    sum1 += __shfl_xor_sync(0xffffffffu, sum1, 1);
    sum1 += __shfl_xor_sync(0xffffffffu, sum1, 2);
    l0 = l0*c0 + sum0;  l1 = l1*c1 + sum1;
    m0 = mn0;  m1 = mn1;
    #pragma unroll
    for (int nt = 0; nt < 16; nt++){
      O[nt][0] *= c0; O[nt][1] *= c0;
      O[nt][2] *= c1; O[nt][3] *= c1;
    }

    uint32_t pf[4][4];
    #pragma unroll
    for (int j = 0; j < 4; j++){
      __half2 h0 = __floats2half2_rn(sacc[2*j][0],   sacc[2*j][1]);
      __half2 h1 = __floats2half2_rn(sacc[2*j][2],   sacc[2*j][3]);
      __half2 h2 = __floats2half2_rn(sacc[2*j+1][0], sacc[2*j+1][1]);
      __half2 h3 = __floats2half2_rn(sacc[2*j+1][2], sacc[2*j+1][3]);
      pf[j][0] = *(uint32_t*)&h0;  pf[j][1] = *(uint32_t*)&h1;
      pf[j][2] = *(uint32_t*)&h2;  pf[j][3] = *(uint32_t*)&h3;
    }

    #pragma unroll
    for (int s = 0; s < 4; s++){
      uint32_t bv[16][2];
      #pragma unroll
      for (int p = 0; p < 8; p++)
        LDMX4(bv[p*2][0], bv[p*2][1], bv[p*2+1][0], bv[p*2+1][1],
              svb + (uint32_t)(((p*16 + b_row)*VSTR + s*16 + b_kh) * 2));
      #pragma unroll
      for (int nt = 0; nt < 16; nt++)
        HMMA(O[nt], pf[s], bv[nt]);
    }
    __syncthreads();
  }

  // ---- write unnormalized partials ----
  int q0 = qt*QT + w*16 + g;
  int q1 = q0 + 8;
  long long r0 = ((long long)sp*NZ + z)*KVL + q0;
  long long r1 = r0 + 8;
  float* o0 = Op + r0*HDD + 2*tg;
  float* o1 = Op + r1*HDD + 2*tg;
  #pragma unroll
  for (int nt = 0; nt < 16; nt++){
    *(float2*)(o0 + nt*8) = make_float2(O[nt][0], O[nt][1]);
    *(float2*)(o1 + nt*8) = make_float2(O[nt][2], O[nt][3]);
  }
  if (tg == 0){
    mlp[r0] = make_float2(m0, l0);
    mlp[r1] = make_float2(m1, l1);
  }
}

// ---------------- split-KV combine -> packed half ap ----------------
__global__ __launch_bounds__(128) void k_comb(
    const float* __restrict__ Op, const float2* __restrict__ mlp,
    __half* __restrict__ ap)
{
  int row = blockIdx.x;            // z*KVL + q
  int z = row / KVL;
  int q = row - z*KVL;
  float2 ml0 = mlp[row];
  float2 ml1 = mlp[(long long)NZ*KVL + row];
  float mx = fmaxf(ml0.x, ml1.x);
  float c0 = exp2f(ml0.x - mx);
  float c1 = exp2f(ml1.x - mx);
  float inv = 1.f / (ml0.y*c0 + ml1.y*c1);
  int d = threadIdx.x;
  float o0 = Op[(long long)row*HDD + d];
  float o1 = Op[((long long)NZ*KVL + row)*HDD + d];
  float o = (o0*c0 + o1*c1) * inv;
  int b = z >> 2, h = z & 3;
  long long tok = (q < LT) ? (long long)(b*LT + q) : (long long)(MT + b*NI + (q - LT));
  ap[tok*DM + h*HDD + d] = __float2half_rn(o);
}

// ---------------- fused prologue: emb + mod + eff + weight->half ----------------
__global__ void k_prep(const float* __restrict__ vec,
                       const float* __restrict__ Wi, const float* __restrict__ bi_,
                       const float* __restrict__ Wt, const float* __restrict__ bt_,
                       float* __restrict__ ei, float* __restrict__ et,
                       const float* __restrict__ sp, const float* __restrict__ mw,
                       const float* __restrict__ mb, float* __restrict__ mod,
                       const float* __restrict__ temp, float* __restrict__ eff,
                       const float* __restrict__ c0, __half* __restrict__ o0,
                       const float* __restrict__ c1, __half* __restrict__ o1,
                       const float* __restrict__ c2, __half* __restrict__ o2,
                       const float* __restrict__ c3, __half* __restrict__ o3,
                       const float* __restrict__ c4, __half* __restrict__ o4,
                       const float* __restrict__ c5, __half* __restrict__ o5,
                       const float* __restrict__ c6, __half* __restrict__ o6,
                       const float* __restrict__ c7, __half* __restrict__ o7)
{
  int blk = blockIdx.x;
  if (blk < 64){
    if (blk == 0 && threadIdx.x < NB){
      int b = threadIdx.x;
      float m = 0.25f*(temp[b*NHD+0]+temp[b*NHD+1]+temp[b*NHD+2]+temp[b*NHD+3]);
      eff[b] = SCALE_C / fmaxf(m, 0.1f);
    }
    int idx = blk*256 + threadIdx.x;
    int n = idx & (NI-1);
    int h = (idx >> 11) & (NHD-1);
    int b = idx >> 13;
    int y = n >> 5;
    int x = n & 31;
    float fy = (y + 0.5f)*0.125f - 0.5f;
    float fx = (x + 0.5f)*0.25f  - 0.5f;
    int y0 = (int)floorf(fy); float wy = fy - (float)y0;
    int x0 = (int)floorf(fx); float wx = fx - (float)x0;
    int y0c = min(max(y0,0),7), y1c = min(max(y0+1,0),7);
    int x0c = min(max(x0,0),7), x1c = min(max(x0+1,0),7);
    const float* p = sp + b*64;
    float v = (1.f-wy)*((1.f-wx)*p[y0c*8+x0c] + wx*p[y0c*8+x1c])
            +      wy *((1.f-wx)*p[y1c*8+x0c] + wx*p[y1c*8+x1c]);
    v = v*mw[h] + mb[h];
    v = fminf(fmaxf(v, -2.f), 2.f);
    mod[idx] = expf(v);
  } else if (blk < 112){
    int be = blk - 64;
    int xb = be % 12;
    int b  = (be / 12) & 1;
    int zi = be / 24;
    const float* W  = zi ? Wt  : Wi;
    const float* bs = zi ? bt_ : bi_;
    float* e        = zi ? et  : ei;
    __shared__ float s[DM];
    for (int i = threadIdx.x; i < DM; i += blockDim.x){
      float v = vec[b*DM + i];
      s[i] = v / (1.f + expf(-v));
    }
    __syncthreads();
    int n = xb*256 + threadIdx.x;
    const float* wr = W + (long long)n*DM;
    float acc = 0.f;
    #pragma unroll 8
    for (int k = 0; k < DM; k++) acc += s[k]*wr[k];
    e[b*E6 + n] = acc + bs[n];
  } else {
    int idx = (blk - 112)*256 + threadIdx.x;
    const float4* in; __half2* out; int off;
    if      (idx <  196608){ in=(const float4*)c0; out=(__half2*)o0; off=0; }
    else if (idx <  393216){ in=(const float4*)c1; out=(__half2*)o1; off=196608; }
    else if (idx <  458752){ in=(const float4*)c2; out=(__half2*)o2; off=393216; }
    else if (idx <  524288){ in=(const float4*)c3; out=(__half2*)o3; off=458752; }
    else if (idx <  786432){ in=(const float4*)c4; out=(__half2*)o4; off=524288; }
    else if (idx < 1048576){ in=(const float4*)c5; out=(__half2*)o5; off=786432; }
    else if (idx < 1310720){ in=(const float4*)c6; out=(__half2*)o6; off=1048576; }
    else                   { in=(const float4*)c7; out=(__half2*)o7; off=1310720; }
    int j = idx - off;
    float4 v = in[j];
    out[j*2]   = __floats2half2_rn(v.x, v.y);
    out[j*2+1] = __floats2half2_rn(v.z, v.w);
  }
}

// ---------------- combined rms-norm + adaln modulate -> half ----------------
__global__ __launch_bounds__(128) void k_rmsmod(
    const float* __restrict__ xt, const float* __restrict__ xi,
    const float* __restrict__ wt, const float* __restrict__ wi,
    const float* __restrict__ et, const float* __restrict__ ei,
    int shift_off, int scale_off, __half* __restrict__ out)
{
  int row = blockIdx.x;
  const float* x; const float* w; const float* eb;
  if (row < MT){
    x = xt + (long long)row*DM; w = wt; eb = et + (row/LT)*E6;
  } else {
    int rr = row - MT;
    x = xi + (long long)rr*DM; w = wi; eb = ei + (rr/NI)*E6;
  }
  float4 xv = ((const float4*)x)[threadIdx.x];
  float ss = xv.x*xv.x + xv.y*xv.y + xv.z*xv.z + xv.w*xv.w;
  ss = warpSum(ss);
  __shared__ float red[4];
  int lane = threadIdx.x & 31, wid = threadIdx.x >> 5;
  if (lane==0) red[wid]=ss;
  __syncthreads();
  float tot = red[0]+red[1]+red[2]+red[3];
  float inv = rsqrtf(tot*(1.f/DM) + 1e-6f);
  int c = threadIdx.x*4;
  float ox = xv.x*inv*w[c+0]*(1.f+eb[scale_off+c+0]) + eb[shift_off+c+0];
  float oy = xv.y*inv*w[c+1]*(1.f+eb[scale_off+c+1]) + eb[shift_off+c+1];
  float oz = xv.z*inv*w[c+2]*(1.f+eb[scale_off+c+2]) + eb[shift_off+c+2];
  float ow = xv.w*inv*w[c+3]*(1.f+eb[scale_off+c+3]) + eb[shift_off+c+3];
  __half2* op = (__half2*)(out + (long long)row*DM);
  op[threadIdx.x*2]   = __floats2half2_rn(ox, oy);
  op[threadIdx.x*2+1] = __floats2half2_rn(oz, ow);
}

// ---------------- launch ----------------
#define GETSYMF(var, sym) float* var; cudaGetSymbolAddress((void**)&var, sym)
#define GETSYMH(var, sym) __half* var; cudaGetSymbolAddress((void**)&var, sym)
#define GETSYM2(var, sym) float2* var; cudaGetSymbolAddress((void**)&var, sym)

extern "C" void kernel_launch(void* const* d_in, const int* in_sizes, int n_in,
                              void* d_out, int out_size)
{
  const float* txt          = (const float*)d_in[0];
  const float* img          = (const float*)d_in[1];
  const float* vec          = (const float*)d_in[2];
  const float* rope         = (const float*)d_in[3];
  const float* sol_t        = (const float*)d_in[4];
  const float* sol_s        = (const float*)d_in[5];
  const float* img_adaln_w  = (const float*)d_in[6];
  const float* img_adaln_b  = (const float*)d_in[7];
  const float* img_adaln_nw = (const float*)d_in[8];
  const float* txt_adaln_w  = (const float*)d_in[9];
  const float* txt_adaln_b  = (const float*)d_in[10];
  const float* txt_adaln_nw = (const float*)d_in[11];
  const float* txt_qkv_w    = (const float*)d_in[12];
  const float* img_qkv_w    = (const float*)d_in[13];
  const float* txt_out_w    = (const float*)d_in[14];
  const float* img_out_w    = (const float*)d_in[15];
  const float* sol_mod_w    = (const float*)d_in[16];
  const float* sol_mod_b    = (const float*)d_in[17];
  const float* img_norm2_w  = (const float*)d_in[18];
  const float* txt_norm2_w  = (const float*)d_in[19];
  const float* img_fc1_w    = (const float*)d_in[20];
  const float* img_fc1_b    = (const float*)d_in[21];
  const float* img_fc2_w    = (const float*)d_in[22];
  const float* img_fc2_b    = (const float*)d_in[23];
  const float* txt_fc1_w    = (const float*)d_in[24];
  const float* txt_fc1_b    = (const float*)d_in[25];
  const float* txt_fc2_w    = (const float*)d_in[26];
  const float* txt_fc2_b    = (const float*)d_in[27];
  float* out = (float*)d_out;

  GETSYMF(e_img, d_e_img);  GETSYMF(e_txt, d_e_txt);
  GETSYMF(eff, d_eff);      GETSYMF(mod, d_mod);
  GETSYMH(nrm, d_nrm);
  GETSYMH(Qc, d_Qc);        GETSYMH(Kc, d_Kc);
  GETSYMH(VT, d_VT);
  GETSYMH(ap, d_ap);        GETSYMH(hh, d_h);
  GETSYMF(cc, d_c);         GETSYMF(Op, d_Op);
  GETSYM2(ml, d_ml);
  GETSYMH(wq_t, d_wq_t);    GETSYMH(wq_i, d_wq_i);
  GETSYMH(wo_t, d_wo_t);    GETSYMH(wo_i, d_wo_i);
  GETSYMH(w1_t, d_w1_t);    GETSYMH(w1_i, d_w1_i);
  GETSYMH(w2_t, d_w2_t);    GETSYMH(w2_i, d_w2_i);

  cudaFuncSetAttribute((const void*)tgemm<4>, cudaFuncAttributeMaxDynamicSharedMemorySize, TG_DSMEM4);
  cudaFuncSetAttribute((const void*)tgemm<2>, cudaFuncAttributeMaxDynamicSharedMemorySize, TG_DSMEM2);
  cudaFuncSetAttribute((const void*)k_flash,  cudaFuncAttributeMaxDynamicSharedMemorySize, FL_DSMEM);

  // 1. fused prologue (emb + mod + eff + weights->half)
  k_prep<<<112 + 6144, 256>>>(vec, img_adaln_w, img_adaln_b, txt_adaln_w, txt_adaln_b,
                              e_img, e_txt, sol_s, sol_mod_w, sol_mod_b, mod, sol_t, eff,
                              txt_qkv_w, wq_t, img_qkv_w, wq_i,
                              txt_out_w, wo_t, img_out_w, wo_i,
                              txt_fc1_w, w1_t, img_fc1_w, w1_i,
                              txt_fc2_w, w2_t, img_fc2_w, w2_i);
  // 2. norm1 combined -> half
  k_rmsmod<<<MALL, 128>>>(txt, img, txt_adaln_nw, img_adaln_nw, e_txt, e_img, 0, 512, nrm);
  // 3. QKV GEMM (64-row tiles, ep5 scatter) -> Qc, Kc, VT
  tgemm<2><<<dim3(12, MALL/64, 1), 256, TG_DSMEM2>>>(nrm, wq_t, wq_i, MT,
      Qc, 1536, DM, 1536, 0, 0,
      BIGR, 1, 0, 0, 0, 0, 1.f, eff, 1, BIGR,
      5, nullptr, nullptr, nullptr, nullptr, nullptr, nullptr, 0,
      rope, mod, Qc, Kc, VT);
  // 4. split-KV flash attention -> partial O, (m,l)
  k_flash<<<dim3(KVL/QT, NZ, 2), 128, FL_DSMEM>>>(Qc, Kc, VT, Op, ml, eff);
  // 5. combine splits -> packed half ap
  k_comb<<<NZ*KVL, 128>>>(Op, ml, ap);
  // 6. output projection + residual gate (ep2) -> float cc
  tgemm<2><<<dim3(4, MALL/64, 1), 256, TG_DSMEM2>>>(ap, wo_t, wo_i, MT,
      cc, DM, DM, DM, 0, 0,
      BIGR, 1, 0, 0, 0, 0, 1.f, eff, 1, BIGR,
      2, txt, img, e_txt, e_img, nullptr, nullptr, 1024,
      nullptr, nullptr, nullptr, nullptr, nullptr);
  // 7. norm2 combined -> half
  k_rmsmod<<<MALL, 128>>>(cc, cc + (long long)MT*DM, txt_norm2_w, img_norm2_w,
                          e_txt, e_img, 1536, 2048, nrm);
  // 8. fc1 + bias + gelu (ep3) -> half h
  tgemm<4><<<dim3(16, MALL/128, 1), 256, TG_DSMEM4>>>(nrm, w1_t, w1_i, MT,
      hh, FFD, DM, FFD, 0, 0,
      BIGR, 1, 0, 0, 0, 0, 1.f, eff, 1, BIGR,
      3, nullptr, nullptr, nullptr, nullptr, txt_fc1_b, img_fc1_b, 0,
      nullptr, nullptr, nullptr, nullptr, nullptr);
  // 9. fc2 + bias + gate + residual (ep4) -> d_out
  tgemm<2><<<dim3(4, MALL/64, 1), 256, TG_DSMEM2>>>(hh, w2_t, w2_i, MT,
      out, DM, FFD, DM, 0, 0,
      BIGR, 1, 0, 0, 0, 0, 1.f, eff, 1, BIGR,
      4, cc, nullptr, e_txt, e_img, txt_fc2_b, img_fc2_b, 2560,
      nullptr, nullptr, nullptr, nullptr, nullptr);
}